// round 11
// baseline (speedup 1.0000x reference)
#include <cuda_runtime.h>
#include <cuda_fp16.h>
#include <math.h>
#include <cstdint>

#define TT 256
#define BB 128
#define HH 512
#define DEMB 256
#define PAD_IDX 29999
#define NCLS 5
#define G4H 2048  // 4*HH

__device__ __forceinline__ uint32_t smem_to_u32(const void* p) {
    uint32_t a;
    asm("{ .reg .u64 t; cvta.to.shared.u64 t, %1; cvt.u32.u64 %0, t; }" : "=r"(a) : "l"(p));
    return a;
}
#define CP_ASYNC16(dst, src) \
    asm volatile("cp.async.cg.shared.global [%0], [%1], 16;" :: "r"(dst), "l"(src))
#define CP_COMMIT  asm volatile("cp.async.commit_group;" ::: "memory")
#define CP_WAIT_1  asm volatile("cp.async.wait_group 1;" ::: "memory")
#define CP_WAIT_0  asm volatile("cp.async.wait_group 0;" ::: "memory")

// ========================= scratch (static, no allocs) =======================
__device__ __half g_x0 [(size_t)TT * BB * DEMB];
__device__ __half g_xg0f[(size_t)TT * BB * G4H];
__device__ __half g_xg0r[(size_t)TT * BB * G4H];
__device__ __half g_h0 [(size_t)TT * BB * 2 * HH];
__device__ __half g_xg1f[(size_t)TT * BB * G4H];
__device__ __half g_xg1r[(size_t)BB * G4H];
__device__ __half g_hf0[2 * 2 * BB * HH];
__device__ __half g_hf1[2 * BB * HH];
__device__ float g_h1f [BB * HH];
__device__ float g_hr1 [BB * HH];
__device__ int g_bar0[2 * TT];
__device__ int g_bar1[2 * TT];

__global__ void reset_kernel() {
    int i = threadIdx.x;
    if (i < 2 * TT) { g_bar0[i] = 0; g_bar1[i] = 0; }
}

__device__ __forceinline__ uint32_t pack_h2(float a, float b) {
    __half2 h = __floats2half2_rn(a, b);
    return *(uint32_t*)&h;
}

// ========================= embedding gather (fp16 out) =======================
__global__ void embed_kernel(const int* __restrict__ x,
                             const float* __restrict__ emb,
                             __half* __restrict__ out) {
    int gid = blockIdx.x * blockDim.x + threadIdx.x;
    if (gid >= TT * BB * (DEMB / 4)) return;
    int i4  = gid & 63;
    int row = gid >> 6;
    int t = row / BB;
    int b = row - t * BB;
    int xi = x[b * TT + t];
    float4 v;
    if (xi == PAD_IDX) { v.x = v.y = v.z = v.w = 0.f; }
    else               { v = ((const float4*)emb)[(size_t)xi * 64 + i4]; }
    uint2 p;
    p.x = pack_h2(v.x, v.y);
    p.y = pack_h2(v.z, v.w);
    ((uint2*)out)[gid] = p;
}

// ========================= mma primitives ====================================
__device__ __forceinline__ void ldsm4(uint32_t* r, uint32_t addr) {
    asm volatile("ldmatrix.sync.aligned.m8n8.x4.shared.b16 {%0,%1,%2,%3}, [%4];"
        : "=r"(r[0]), "=r"(r[1]), "=r"(r[2]), "=r"(r[3]) : "r"(addr));
}
__device__ __forceinline__ void mma_f16(float* d, const uint32_t* a,
                                        uint32_t b0, uint32_t b1) {
    asm volatile("mma.sync.aligned.m16n8k16.row.col.f32.f16.f16.f32 "
        "{%0,%1,%2,%3}, {%4,%5,%6,%7}, {%8,%9}, {%0,%1,%2,%3};"
        : "+f"(d[0]), "+f"(d[1]), "+f"(d[2]), "+f"(d[3])
        : "r"(a[0]), "r"(a[1]), "r"(a[2]), "r"(a[3]), "r"(b0), "r"(b1));
}
__device__ __forceinline__ void splitw_store(uint32_t hiA, uint32_t loA, float4 v) {
    __half h0 = __float2half_rn(v.x), h1 = __float2half_rn(v.y);
    __half h2 = __float2half_rn(v.z), h3 = __float2half_rn(v.w);
    float r0 = v.x - __half2float(h0), r1 = v.y - __half2float(h1);
    float r2 = v.z - __half2float(h2), r3 = v.w - __half2float(h3);
    uint32_t hp0 = pack_h2(__half2float(h0), __half2float(h1));
    uint32_t hp1 = pack_h2(__half2float(h2), __half2float(h3));
    uint32_t lp0 = pack_h2(r0, r1);
    uint32_t lp1 = pack_h2(r2, r3);
    asm volatile("st.shared.v2.b32 [%0], {%1, %2};" :: "r"(hiA), "r"(hp0), "r"(hp1) : "memory");
    asm volatile("st.shared.v2.b32 [%0], {%1, %2};" :: "r"(loA), "r"(lp0), "r"(lp1) : "memory");
}

// ========================= fp16-A GEMM: C(fp16) = A*W^T + bias ===============
#define KC  32
#define LDH 40
#define GA_BYTES (128 * LDH * 2)

__global__ __launch_bounds__(256, 2) void gemm_mma(const __half* __restrict__ A,
                                                   const float* __restrict__ W,
                                                   const float* __restrict__ bias,
                                                   __half* __restrict__ C,
                                                   int M, int N, int K) {
    __shared__ __align__(16) __half gsm[4 * 128 * LDH];
    const uint32_t sb  = smem_to_u32(gsm);
    const uint32_t AH0 = sb, AH1 = sb + GA_BYTES;
    const uint32_t BH  = sb + 2 * GA_BYTES, BL = BH + GA_BYTES;

    const int tid  = threadIdx.x;
    const int lane = tid & 31;
    const int wid  = tid >> 5;
    const int wm   = wid & 3;
    const int wn   = wid >> 2;
    const int bm   = blockIdx.y * 128;
    const int bn   = blockIdx.x * 128;

    float acc[2][8][4];
#pragma unroll
    for (int i = 0; i < 2; i++)
#pragma unroll
        for (int j = 0; j < 8; j++)
#pragma unroll
            for (int k = 0; k < 4; k++) acc[i][j][k] = 0.f;

    const uint32_t a_row = lane & 15;
    const uint32_t a_col = (lane >> 4) << 3;
    const uint32_t b_n   = (lane & 7) + ((lane >> 4) << 3);
    const uint32_t b_k   = ((lane >> 3) & 1) << 3;

    const int s_row = tid >> 2, s_c8 = tid & 3;
    const int w_row = tid >> 3, w_c4 = tid & 7;

    float4 vw[4];
#pragma unroll
    for (int i = 0; i < 2; i++) {
        int row = s_row + i * 64;
        CP_ASYNC16(AH0 + (row * LDH + s_c8 * 8) * 2,
                   A + (size_t)(bm + row) * K + s_c8 * 8);
    }
    CP_COMMIT;
#pragma unroll
    for (int i = 0; i < 4; i++) {
        int row = w_row + i * 32;
        vw[i] = *(const float4*)(W + (size_t)(bn + row) * K + w_c4 * 4);
    }

    const int nch = K / KC;
    for (int ch = 0; ch < nch; ch++) {
        const int kb = ch * KC;
        if (ch + 1 < nch) {
            uint32_t dst = ((ch + 1) & 1) ? AH1 : AH0;
#pragma unroll
            for (int i = 0; i < 2; i++) {
                int row = s_row + i * 64;
                CP_ASYNC16(dst + (row * LDH + s_c8 * 8) * 2,
                           A + (size_t)(bm + row) * K + kb + KC + s_c8 * 8);
            }
            CP_COMMIT;
        }
#pragma unroll
        for (int i = 0; i < 4; i++) {
            int row = w_row + i * 32;
            uint32_t off = (row * LDH + w_c4 * 4) * 2;
            splitw_store(BH + off, BL + off, vw[i]);
        }
        if (ch + 1 < nch) {
#pragma unroll
            for (int i = 0; i < 4; i++) {
                int row = w_row + i * 32;
                vw[i] = *(const float4*)(W + (size_t)(bn + row) * K + kb + KC + w_c4 * 4);
            }
        }
        if (ch + 1 < nch) { CP_WAIT_1; } else { CP_WAIT_0; }
        __syncthreads();

        const uint32_t AH = (ch & 1) ? AH1 : AH0;
#pragma unroll
        for (int ks = 0; ks < KC; ks += 16) {
            uint32_t ah[2][4];
#pragma unroll
            for (int ma = 0; ma < 2; ma++)
                ldsm4(ah[ma], AH + ((wm * 32 + ma * 16 + a_row) * LDH + ks + a_col) * 2);
#pragma unroll
            for (int bg = 0; bg < 4; bg++) {
                uint32_t boff = ((wn * 64 + bg * 16 + b_n) * LDH + ks + b_k) * 2;
                uint32_t bh[4], bl[4];
                ldsm4(bh, BH + boff);
                ldsm4(bl, BL + boff);
#pragma unroll
                for (int ma = 0; ma < 2; ma++) {
#pragma unroll
                    for (int na = 0; na < 2; na++) {
                        float* d = acc[ma][bg * 2 + na];
                        mma_f16(d, ah[ma], bh[na * 2], bh[na * 2 + 1]);
                        mma_f16(d, ah[ma], bl[na * 2], bl[na * 2 + 1]);
                    }
                }
            }
        }
        __syncthreads();
    }

#pragma unroll
    for (int ma = 0; ma < 2; ma++) {
        int row0 = bm + wm * 32 + ma * 16 + (lane >> 2);
#pragma unroll
        for (int na = 0; na < 8; na++) {
            int col = bn + wn * 64 + na * 8 + (lane & 3) * 2;
            float b0 = bias[col], b1 = bias[col + 1];
            *(uint32_t*)(C + (size_t)row0 * N + col) =
                pack_h2(acc[ma][na][0] + b0, acc[ma][na][1] + b1);
            *(uint32_t*)(C + (size_t)(row0 + 8) * N + col) =
                pack_h2(acc[ma][na][2] + b0, acc[ma][na][3] + b1);
        }
    }
}

__device__ __forceinline__ float sigmoidf_(float v) { return 1.f / (1.f + expf(-v)); }

// ========================= layer-0 scan: warp data path + CTA barrier ========
// 64 CTAs = 2 dirs x 32 slices of 16 units (n = gate*16 + u). Each warp owns
// 16 batches with private double-buffered staging (no syncthreads inside the
// step's data path). End-of-step barrier is the PROVEN R9 CTA-wide protocol
// (fence -> syncthreads -> tid0 atomic+spin(32) -> syncthreads).
#define W_STR 520
#define A0_STR 136
#define W0_BYTES (64 * W_STR * 2)           // 66560 per split
#define S0W_W (2 * W0_BYTES)                // 133120
#define A0_BUF (16 * A0_STR * 2)            // 4352
#define S0W_SMEM (S0W_W + 8 * 2 * A0_BUF)   // 202752

__device__ __forceinline__ void stage16(uint32_t buf, const __half* hs,
                                        int kb, int lane) {
#pragma unroll
    for (int i = 0; i < 8; i++) {
        int e = lane + i * 32;
        int row = e >> 4, seg = e & 15;
        CP_ASYNC16(buf + (row * A0_STR + seg * 8) * 2,
                   hs + (size_t)row * HH + kb + seg * 8);
    }
}

__device__ __forceinline__ void mma_c0(uint32_t buf, uint32_t WHI, uint32_t WLO,
                                       int kg0, uint32_t a_row, uint32_t a_col,
                                       uint32_t b_n, uint32_t b_k,
                                       float acc[8][4]) {
#pragma unroll
    for (int kk = 0; kk < 8; kk++) {
        uint32_t a[4];
        ldsm4(a, buf + (a_row * A0_STR + kk * 16 + a_col) * 2);
        int kg = kg0 + kk * 16;
#pragma unroll
        for (int n0 = 0; n0 < 4; n0++) {
            uint32_t wh[4], wl[4];
            ldsm4(wh, WHI + ((n0 * 16 + b_n) * W_STR + kg + b_k) * 2);
            ldsm4(wl, WLO + ((n0 * 16 + b_n) * W_STR + kg + b_k) * 2);
            mma_f16(acc[n0 * 2],     a, wh[0], wh[1]);
            mma_f16(acc[n0 * 2],     a, wl[0], wl[1]);
            mma_f16(acc[n0 * 2 + 1], a, wh[2], wh[3]);
            mma_f16(acc[n0 * 2 + 1], a, wl[2], wl[3]);
        }
    }
}

__global__ __launch_bounds__(256, 1) void scan0_warp(
    const __half* __restrict__ xgf, const __half* __restrict__ xgr,
    const float* __restrict__ whhf, const float* __restrict__ whhr,
    const float* __restrict__ bhhf, const float* __restrict__ bhhr,
    __half* __restrict__ hrec, __half* __restrict__ houth,
    int* __restrict__ bar) {
    extern __shared__ __align__(16) char smem[];
    const uint32_t sb  = smem_to_u32(smem);
    const uint32_t WHI = sb, WLO = sb + W0_BYTES;
    const uint32_t ABASE = sb + S0W_W;

    const int tid = threadIdx.x, lane = tid & 31, wid = tid >> 5;
    const int dir   = blockIdx.x >> 5;
    const int slice = blockIdx.x & 31;
    const int j0    = slice * 16;

    const float* whh = dir ? whhr : whhf;
    const float* bhh = dir ? bhhr : bhhf;
    const __half* xg = dir ? xgr  : xgf;
    int* barp = bar + dir * TT;
    __half* hbuf = hrec + (size_t)dir * 2 * BB * HH;

    // W slice -> smem hi/lo: rows n = g*16+u <- whh[g*512 + j0 + u]
#pragma unroll
    for (int i = 0; i < 32; i++) {
        int idx = tid + i * 256;
        int n = idx >> 7, c4 = idx & 127;
        int grow = (n >> 4) * 512 + j0 + (n & 15);
        float4 v = *(const float4*)(whh + (size_t)grow * 512 + c4 * 4);
        uint32_t off = (n * W_STR + c4 * 4) * 2;
        splitw_store(WHI + off, WLO + off, v);
    }
    __syncthreads();

    const uint32_t a_row = lane & 15;
    const uint32_t a_col = (lane >> 4) << 3;
    const uint32_t b_n   = (lane & 7) + ((lane >> 4) << 3);
    const uint32_t b_k   = ((lane >> 3) & 1) << 3;
    const int q = lane & 3;
    const int r = lane >> 2;
    const int b0 = wid * 16 + r;
    const uint32_t wbuf0 = ABASE + wid * 2 * A0_BUF;
    const uint32_t wbuf1 = wbuf0 + A0_BUF;

    float bias[4][2][2];
#pragma unroll
    for (int g = 0; g < 4; g++)
#pragma unroll
        for (int a1 = 0; a1 < 2; a1++)
#pragma unroll
            for (int cc = 0; cc < 2; cc++)
                bias[g][a1][cc] = bhh[g * 512 + j0 + a1 * 8 + q * 2 + cc];

    float c[2][4];
#pragma unroll
    for (int i = 0; i < 2; i++)
#pragma unroll
        for (int k = 0; k < 4; k++) c[i][k] = 0.f;

    for (int step = 0; step < TT; step++) {
        const int t = dir ? (TT - 1 - step) : step;

        uint32_t xr[4][2][2];
#pragma unroll
        for (int g = 0; g < 4; g++)
#pragma unroll
            for (int rp = 0; rp < 2; rp++)
#pragma unroll
                for (int a1 = 0; a1 < 2; a1++)
                    xr[g][rp][a1] = *(const uint32_t*)(
                        xg + ((size_t)t * BB + b0 + rp * 8) * G4H
                           + g * 512 + j0 + a1 * 8 + q * 2);

        float acc[8][4];
#pragma unroll
        for (int a = 0; a < 8; a++)
#pragma unroll
            for (int k = 0; k < 4; k++) acc[a][k] = 0.f;

        if (step > 0) {
            const __half* hs = hbuf + (size_t)((step - 1) & 1) * BB * HH
                             + (size_t)(wid * 16) * HH;
            stage16(wbuf0, hs, 0, lane);   CP_COMMIT;
            stage16(wbuf1, hs, 128, lane); CP_COMMIT;
            CP_WAIT_1;
            mma_c0(wbuf0, WHI, WLO, 0, a_row, a_col, b_n, b_k, acc);
            stage16(wbuf0, hs, 256, lane); CP_COMMIT;
            CP_WAIT_1;
            mma_c0(wbuf1, WHI, WLO, 128, a_row, a_col, b_n, b_k, acc);
            stage16(wbuf1, hs, 384, lane); CP_COMMIT;
            CP_WAIT_1;
            mma_c0(wbuf0, WHI, WLO, 256, a_row, a_col, b_n, b_k, acc);
            CP_WAIT_0;
            mma_c0(wbuf1, WHI, WLO, 384, a_row, a_col, b_n, b_k, acc);
        }

        __half* dh = hbuf + (size_t)(step & 1) * BB * HH;
#pragma unroll
        for (int rp = 0; rp < 2; rp++) {
            const int b = b0 + rp * 8;
#pragma unroll
            for (int a1 = 0; a1 < 2; a1++) {
                float hv2[2];
#pragma unroll
                for (int cc = 0; cc < 2; cc++) {
                    const int vi = rp * 2 + cc;
                    float2 x0 = __half22float2(*(__half2*)&xr[0][rp][a1]);
                    float2 x1 = __half22float2(*(__half2*)&xr[1][rp][a1]);
                    float2 x2 = __half22float2(*(__half2*)&xr[2][rp][a1]);
                    float2 x3 = __half22float2(*(__half2*)&xr[3][rp][a1]);
                    float gi = acc[0 + a1][vi] + (cc ? x0.y : x0.x) + bias[0][a1][cc];
                    float gf = acc[2 + a1][vi] + (cc ? x1.y : x1.x) + bias[1][a1][cc];
                    float gg = acc[4 + a1][vi] + (cc ? x2.y : x2.x) + bias[2][a1][cc];
                    float go = acc[6 + a1][vi] + (cc ? x3.y : x3.x) + bias[3][a1][cc];
                    float cv = sigmoidf_(gf) * c[rp][a1 * 2 + cc]
                             + sigmoidf_(gi) * tanhf(gg);
                    c[rp][a1 * 2 + cc] = cv;
                    hv2[cc] = sigmoidf_(go) * tanhf(cv);
                }
                uint32_t p = pack_h2(hv2[0], hv2[1]);
                const int uoff = j0 + a1 * 8 + q * 2;
                *(uint32_t*)(dh + (size_t)b * HH + uoff) = p;
                *(uint32_t*)(houth + ((size_t)t * BB + b) * 1024 + dir * 512 + uoff) = p;
            }
        }

        // PROVEN CTA-wide step barrier (32 CTAs per direction)
        if (step < TT - 1) {
            __threadfence();
            __syncthreads();
            if (tid == 0) {
                atomicAdd(barp + step, 1);
                while (((volatile int*)barp)[step] < 32) {}
            }
            __syncthreads();
        }
    }
}

// ========================= layer-1 scan (R9 proven template, <false> only) ===
#define A_STR 264
#define W_SPL_BYTES (32 * W_STR * 2)
#define SCAN_W_BYTES (2 * W_SPL_BYTES)                    // 66560
#define SCAN1_SMEM (SCAN_W_BYTES + 2 * 64 * A_STR * 2)    // 134144

template<int MC>
__device__ __forceinline__ void stage_chunk(uint32_t dst, const __half* hs,
                                            int bbase, int kb, int tid) {
#pragma unroll
    for (int i = 0; i < MC / 8; i++) {
        int e = tid + i * 256;
        int row = e >> 5, seg = e & 31;
        const __half* src = hs + (size_t)(bbase + row) * HH + kb + seg * 8;
        CP_ASYNC16(dst + (row * A_STR + seg * 8) * 2, src);
    }
}

__device__ __forceinline__ void mma_chunk(uint32_t AB, uint32_t WHI, uint32_t WLO,
                                          int mrow, int kg0,
                                          uint32_t a_row, uint32_t a_col,
                                          uint32_t b_n, uint32_t b_k,
                                          float acc[4][4]) {
#pragma unroll
    for (int kk = 0; kk < 16; kk++) {
        uint32_t a[4];
        ldsm4(a, AB + ((mrow + a_row) * A_STR + kk * 16 + a_col) * 2);
        int kg = kg0 + kk * 16;
        uint32_t bh0[4], bh1[4], bl0[4], bl1[4];
        ldsm4(bh0, WHI + (b_n * W_STR + kg + b_k) * 2);
        ldsm4(bh1, WHI + ((16 + b_n) * W_STR + kg + b_k) * 2);
        ldsm4(bl0, WLO + (b_n * W_STR + kg + b_k) * 2);
        ldsm4(bl1, WLO + ((16 + b_n) * W_STR + kg + b_k) * 2);
        mma_f16(acc[0], a, bh0[0], bh0[1]);
        mma_f16(acc[0], a, bl0[0], bl0[1]);
        mma_f16(acc[1], a, bh0[2], bh0[3]);
        mma_f16(acc[1], a, bl0[2], bl0[3]);
        mma_f16(acc[2], a, bh1[0], bh1[1]);
        mma_f16(acc[2], a, bl1[0], bl1[1]);
        mma_f16(acc[3], a, bh1[2], bh1[3]);
        mma_f16(acc[3], a, bl1[2], bl1[3]);
    }
}

__global__ __launch_bounds__(256, 1) void scan1_mma(
    const __half* __restrict__ xg,
    const float* __restrict__ whh, const float* __restrict__ bhh,
    __half* __restrict__ hrec, float* __restrict__ houtf,
    int* __restrict__ bar) {
    constexpr int MC = 64;
    constexpr int ASZ = MC * A_STR * 2;
    extern __shared__ __align__(16) char smem[];
    const uint32_t sb  = smem_to_u32(smem);
    const uint32_t WHI = sb, WLO = sb + W_SPL_BYTES;
    const uint32_t AB0 = sb + SCAN_W_BYTES, AB1 = AB0 + ASZ;

    const int tid = threadIdx.x, lane = tid & 31, wid = tid >> 5;
    const int grp   = blockIdx.x >> 6;
    const int slice = blockIdx.x & 63;
    const int j0    = slice * 8;
    const int bbase = grp * 64;

    int* barp = bar + grp * TT;
    __half* hbuf = hrec;

#pragma unroll
    for (int i = 0; i < 16; i++) {
        int idx = tid + i * 256;
        int n = idx >> 7, c4 = idx & 127;
        int grow = (n >> 3) * 512 + j0 + (n & 7);
        float4 v = *(const float4*)(whh + (size_t)grow * 512 + c4 * 4);
        uint32_t off = (n * W_STR + c4 * 4) * 2;
        splitw_store(WHI + off, WLO + off, v);
    }
    __syncthreads();

    const uint32_t a_row = lane & 15;
    const uint32_t a_col = (lane >> 4) << 3;
    const uint32_t b_n   = (lane & 7) + ((lane >> 4) << 3);
    const uint32_t b_k   = ((lane >> 3) & 1) << 3;
    const int r = lane >> 2;
    const int u = (lane & 3) * 2;
    const int wm = wid & 3;
    const int mrow = wm * 16;
    const bool owner = (wid < 4);

    float bias[4][2];
#pragma unroll
    for (int g = 0; g < 4; g++) {
        bias[g][0] = bhh[g * 512 + j0 + u];
        bias[g][1] = bhh[g * 512 + j0 + u + 1];
    }
    float c[4] = {0.f, 0.f, 0.f, 0.f};

    for (int step = 0; step < TT; step++) {
        const int t = step;

        uint32_t xr[4][2];
        if (owner) {
            const __half* xp = xg + ((size_t)(t * BB + bbase + mrow + r)) * G4H + j0 + u;
#pragma unroll
            for (int g = 0; g < 4; g++)
#pragma unroll
                for (int rp = 0; rp < 2; rp++)
                    xr[g][rp] = *(const uint32_t*)(xp + (size_t)rp * 8 * G4H + g * 512);
        }

        float acc[4][4];
#pragma unroll
        for (int g = 0; g < 4; g++)
#pragma unroll
            for (int k = 0; k < 4; k++) acc[g][k] = 0.f;

        if (step > 0) {
            const int rpar = (step - 1) & 1;
            const __half* hs = hbuf + (size_t)rpar * BB * HH;
            stage_chunk<MC>(AB0, hs, bbase, 0, tid);   CP_COMMIT;
            stage_chunk<MC>(AB1, hs, bbase, 256, tid); CP_COMMIT;
            CP_WAIT_0;
            __syncthreads();
            const int ks = wid >> 2;
            mma_chunk(ks ? AB1 : AB0, WHI, WLO, mrow, ks * 256,
                      a_row, a_col, b_n, b_k, acc);
        }

        __syncthreads();
        if (wid >= 4) {
            uint32_t base = AB0 + ((wid - 4) * 32 + lane) * 4;
#pragma unroll
            for (int f = 0; f < 16; f++)
                *(float*)(smem + (base - sb) + f * 512) = acc[f >> 2][f & 3];
        }
        __syncthreads();
        if (wid < 4) {
            uint32_t base = AB0 + (wid * 32 + lane) * 4;
#pragma unroll
            for (int f = 0; f < 16; f++)
                acc[f >> 2][f & 3] += *(float*)(smem + (base - sb) + f * 512);
        }

        if (owner) {
            const int wpar = step & 1;
            __half* dh = hbuf + (size_t)wpar * BB * HH;
#pragma unroll
            for (int rp = 0; rp < 2; rp++) {
                const int b = bbase + mrow + r + rp * 8;
                float hv2[2];
#pragma unroll
                for (int cc = 0; cc < 2; cc++) {
                    const int k = rp * 2 + cc;
                    float2 x0 = __half22float2(*(__half2*)&xr[0][rp]);
                    float2 x1 = __half22float2(*(__half2*)&xr[1][rp]);
                    float2 x2 = __half22float2(*(__half2*)&xr[2][rp]);
                    float2 x3 = __half22float2(*(__half2*)&xr[3][rp]);
                    float gi = acc[0][k] + (cc ? x0.y : x0.x) + bias[0][cc];
                    float gf = acc[1][k] + (cc ? x1.y : x1.x) + bias[1][cc];
                    float gg = acc[2][k] + (cc ? x2.y : x2.x) + bias[2][cc];
                    float go = acc[3][k] + (cc ? x3.y : x3.x) + bias[3][cc];
                    float cv = sigmoidf_(gf) * c[k] + sigmoidf_(gi) * tanhf(gg);
                    c[k] = cv;
                    hv2[cc] = sigmoidf_(go) * tanhf(cv);
                }
                if (t == TT - 1) {
                    *(float2*)(houtf + (size_t)b * HH + j0 + u) =
                        make_float2(hv2[0], hv2[1]);
                }
                *(uint32_t*)(dh + (size_t)b * HH + j0 + u) = pack_h2(hv2[0], hv2[1]);
            }
        }

        if (step < TT - 1) {
            __threadfence();
            __syncthreads();
            if (tid == 0) {
                atomicAdd(barp + step, 1);
                while (((volatile int*)barp)[step] < 64) {}
            }
            __syncthreads();
        }
    }
}

// ========================= layer-1 reverse at t = T-1 ========================
__global__ void hr_last_kernel(const __half* __restrict__ xg,
                               const float* __restrict__ bhh,
                               float* __restrict__ hr) {
    int idx = blockIdx.x * blockDim.x + threadIdx.x;
    if (idx >= BB * HH) return;
    int b = idx >> 9, j = idx & 511;
    float gi = __half2float(xg[(size_t)b * G4H + j])        + bhh[j];
    float gg = __half2float(xg[(size_t)b * G4H + 1024 + j]) + bhh[1024 + j];
    float go = __half2float(xg[(size_t)b * G4H + 1536 + j]) + bhh[1536 + j];
    float cv = sigmoidf_(gi) * tanhf(gg);
    hr[idx] = sigmoidf_(go) * tanhf(cv);
}

// ========================= final projection ==================================
__global__ void out_kernel(const float* __restrict__ hf, const float* __restrict__ hr,
                           const float* __restrict__ wout, const float* __restrict__ bout,
                           float* __restrict__ out) {
    int b = blockIdx.x;
    int warp = threadIdx.x >> 5;
    int lane = threadIdx.x & 31;
    float s = 0.f;
    for (int k = lane; k < 512; k += 32) s += hf[(size_t)b * HH + k] * wout[warp * 1024 + k];
    for (int k = lane; k < 512; k += 32) s += hr[(size_t)b * HH + k] * wout[warp * 1024 + 512 + k];
#pragma unroll
    for (int off = 16; off; off >>= 1) s += __shfl_xor_sync(0xffffffffu, s, off);
    if (lane == 0) out[b * NCLS + warp] = s + bout[warp];
}

// ========================= host launch =======================================
extern "C" void kernel_launch(void* const* d_in, const int* in_sizes, int n_in,
                              void* d_out, int out_size) {
    const int*   x     = (const int*)  d_in[0];
    const float* emb   = (const float*)d_in[1];
    const float* wih0f = (const float*)d_in[2];
    const float* whh0f = (const float*)d_in[3];
    const float* bih0f = (const float*)d_in[4];
    const float* bhh0f = (const float*)d_in[5];
    const float* wih0r = (const float*)d_in[6];
    const float* whh0r = (const float*)d_in[7];
    const float* bih0r = (const float*)d_in[8];
    const float* bhh0r = (const float*)d_in[9];
    const float* wih1f = (const float*)d_in[10];
    const float* whh1f = (const float*)d_in[11];
    const float* bih1f = (const float*)d_in[12];
    const float* bhh1f = (const float*)d_in[13];
    const float* wih1r = (const float*)d_in[14];
    const float* whh1r = (const float*)d_in[15]; (void)whh1r;
    const float* bih1r = (const float*)d_in[16];
    const float* bhh1r = (const float*)d_in[17];
    const float* wout  = (const float*)d_in[18];
    const float* bout  = (const float*)d_in[19];
    float* out = (float*)d_out;

    __half *p_x0, *p_h0, *p_hf0, *p_hf1, *p_xg0f, *p_xg0r, *p_xg1f, *p_xg1r;
    float *p_h1f, *p_hr1;
    int *p_bar0, *p_bar1;
    cudaGetSymbolAddress((void**)&p_x0,   g_x0);
    cudaGetSymbolAddress((void**)&p_xg0f, g_xg0f);
    cudaGetSymbolAddress((void**)&p_xg0r, g_xg0r);
    cudaGetSymbolAddress((void**)&p_h0,   g_h0);
    cudaGetSymbolAddress((void**)&p_xg1f, g_xg1f);
    cudaGetSymbolAddress((void**)&p_xg1r, g_xg1r);
    cudaGetSymbolAddress((void**)&p_hf0,  g_hf0);
    cudaGetSymbolAddress((void**)&p_hf1,  g_hf1);
    cudaGetSymbolAddress((void**)&p_h1f,  g_h1f);
    cudaGetSymbolAddress((void**)&p_hr1,  g_hr1);
    cudaGetSymbolAddress((void**)&p_bar0, g_bar0);
    cudaGetSymbolAddress((void**)&p_bar1, g_bar1);

    cudaFuncSetAttribute(scan0_warp, cudaFuncAttributeMaxDynamicSharedMemorySize, S0W_SMEM);
    cudaFuncSetAttribute(scan1_mma,  cudaFuncAttributeMaxDynamicSharedMemorySize, SCAN1_SMEM);

    reset_kernel<<<1, 512>>>();
    embed_kernel<<<(TT * BB * (DEMB / 4) + 255) / 256, 256>>>(x, emb, p_x0);

    dim3 gBig(G4H / 128, (TT * BB) / 128);   // (16, 256)
    gemm_mma<<<gBig, 256>>>(p_x0, wih0f, bih0f, p_xg0f, TT * BB, G4H, DEMB);
    gemm_mma<<<gBig, 256>>>(p_x0, wih0r, bih0r, p_xg0r, TT * BB, G4H, DEMB);

    scan0_warp<<<64, 256, S0W_SMEM>>>(p_xg0f, p_xg0r, whh0f, whh0r,
                                      bhh0f, bhh0r, p_hf0, p_h0, p_bar0);

    gemm_mma<<<gBig, 256>>>(p_h0, wih1f, bih1f, p_xg1f, TT * BB, G4H, 2 * HH);
    gemm_mma<<<dim3(G4H / 128, 1), 256>>>(
        p_h0 + (size_t)(TT - 1) * BB * 1024, wih1r, bih1r, p_xg1r, BB, G4H, 2 * HH);

    scan1_mma<<<128, 256, SCAN1_SMEM>>>(p_xg1f, whh1f, bhh1f, p_hf1, p_h1f, p_bar1);

    hr_last_kernel<<<(BB * HH) / 256, 256>>>(p_xg1r, bhh1r, p_hr1);

    out_kernel<<<BB, 160>>>(p_h1f, p_hr1, wout, bout, out);
}

// round 12
// speedup vs baseline: 1.1344x; 1.1344x over previous
#include <cuda_runtime.h>
#include <cuda_fp16.h>
#include <math.h>
#include <cstdint>

#define TT 256
#define BB 128
#define HH 512
#define DEMB 256
#define PAD_IDX 29999
#define NCLS 5
#define G4H 2048  // 4*HH

// distributed barrier: 8 sub-counters x 32-int (128B) spacing per (group, step)
#define BAR_SUB 8
#define BAR_SPC 32
#define BAR_STEP (BAR_SUB * BAR_SPC)        // 256 ints per step
#define BAR_GRP  (TT * BAR_STEP)            // per group

__device__ __forceinline__ uint32_t smem_to_u32(const void* p) {
    uint32_t a;
    asm("{ .reg .u64 t; cvta.to.shared.u64 t, %1; cvt.u32.u64 %0, t; }" : "=r"(a) : "l"(p));
    return a;
}
#define CP_ASYNC16(dst, src) \
    asm volatile("cp.async.cg.shared.global [%0], [%1], 16;" :: "r"(dst), "l"(src))
#define CP_COMMIT  asm volatile("cp.async.commit_group;" ::: "memory")
#define CP_WAIT_1  asm volatile("cp.async.wait_group 1;" ::: "memory")
#define CP_WAIT_0  asm volatile("cp.async.wait_group 0;" ::: "memory")

// ========================= scratch (static, no allocs) =======================
__device__ __half g_x0 [(size_t)TT * BB * DEMB];
__device__ __half g_xg0f[(size_t)TT * BB * G4H];
__device__ __half g_xg0r[(size_t)TT * BB * G4H];
__device__ __half g_h0 [(size_t)TT * BB * 2 * HH];
__device__ __half g_xg1f[(size_t)TT * BB * G4H];
__device__ __half g_xg1r[(size_t)BB * G4H];
__device__ __half g_hf0[2 * 2 * BB * HH];
__device__ __half g_hf1[2 * BB * HH];
__device__ float g_h1f [BB * HH];
__device__ float g_hr1 [BB * HH];
__device__ int g_bar0[2 * BAR_GRP];
__device__ int g_bar1[2 * BAR_GRP];

__global__ void reset_kernel() {
    int n = 2 * BAR_GRP;
    for (int i = blockIdx.x * blockDim.x + threadIdx.x; i < n;
         i += gridDim.x * blockDim.x) {
        g_bar0[i] = 0;
        g_bar1[i] = 0;
    }
}

__device__ __forceinline__ uint32_t pack_h2(float a, float b) {
    __half2 h = __floats2half2_rn(a, b);
    return *(uint32_t*)&h;
}

// distributed barrier: arrive on sub-counter, poll sum of all 8
__device__ __forceinline__ void bar_arrive_wait(int* base, int sub, int target) {
    atomicAdd(base + sub * BAR_SPC, 1);
    for (;;) {
        int sum = 0;
#pragma unroll
        for (int s = 0; s < BAR_SUB; s++) {
            int v;
            asm volatile("ld.global.cg.b32 %0, [%1];" : "=r"(v)
                         : "l"(base + s * BAR_SPC));
            sum += v;
        }
        if (sum >= target) break;
        __nanosleep(32);
    }
}

// ========================= embedding gather (fp16 out) =======================
__global__ void embed_kernel(const int* __restrict__ x,
                             const float* __restrict__ emb,
                             __half* __restrict__ out) {
    int gid = blockIdx.x * blockDim.x + threadIdx.x;
    if (gid >= TT * BB * (DEMB / 4)) return;
    int i4  = gid & 63;
    int row = gid >> 6;
    int t = row / BB;
    int b = row - t * BB;
    int xi = x[b * TT + t];
    float4 v;
    if (xi == PAD_IDX) { v.x = v.y = v.z = v.w = 0.f; }
    else               { v = ((const float4*)emb)[(size_t)xi * 64 + i4]; }
    uint2 p;
    p.x = pack_h2(v.x, v.y);
    p.y = pack_h2(v.z, v.w);
    ((uint2*)out)[gid] = p;
}

// ========================= mma primitives ====================================
__device__ __forceinline__ void ldsm4(uint32_t* r, uint32_t addr) {
    asm volatile("ldmatrix.sync.aligned.m8n8.x4.shared.b16 {%0,%1,%2,%3}, [%4];"
        : "=r"(r[0]), "=r"(r[1]), "=r"(r[2]), "=r"(r[3]) : "r"(addr));
}
__device__ __forceinline__ void mma_f16(float* d, const uint32_t* a,
                                        uint32_t b0, uint32_t b1) {
    asm volatile("mma.sync.aligned.m16n8k16.row.col.f32.f16.f16.f32 "
        "{%0,%1,%2,%3}, {%4,%5,%6,%7}, {%8,%9}, {%0,%1,%2,%3};"
        : "+f"(d[0]), "+f"(d[1]), "+f"(d[2]), "+f"(d[3])
        : "r"(a[0]), "r"(a[1]), "r"(a[2]), "r"(a[3]), "r"(b0), "r"(b1));
}
__device__ __forceinline__ void splitw_store(uint32_t hiA, uint32_t loA, float4 v) {
    __half h0 = __float2half_rn(v.x), h1 = __float2half_rn(v.y);
    __half h2 = __float2half_rn(v.z), h3 = __float2half_rn(v.w);
    float r0 = v.x - __half2float(h0), r1 = v.y - __half2float(h1);
    float r2 = v.z - __half2float(h2), r3 = v.w - __half2float(h3);
    uint32_t hp0 = pack_h2(__half2float(h0), __half2float(h1));
    uint32_t hp1 = pack_h2(__half2float(h2), __half2float(h3));
    uint32_t lp0 = pack_h2(r0, r1);
    uint32_t lp1 = pack_h2(r2, r3);
    asm volatile("st.shared.v2.b32 [%0], {%1, %2};" :: "r"(hiA), "r"(hp0), "r"(hp1) : "memory");
    asm volatile("st.shared.v2.b32 [%0], {%1, %2};" :: "r"(loA), "r"(lp0), "r"(lp1) : "memory");
}

// ========================= fp16-A GEMM: C(fp16) = A*W^T + bias ===============
#define KC  32
#define LDH 40
#define GA_BYTES (128 * LDH * 2)

__global__ __launch_bounds__(256, 2) void gemm_mma(const __half* __restrict__ A,
                                                   const float* __restrict__ W,
                                                   const float* __restrict__ bias,
                                                   __half* __restrict__ C,
                                                   int M, int N, int K) {
    __shared__ __align__(16) __half gsm[4 * 128 * LDH];
    const uint32_t sb  = smem_to_u32(gsm);
    const uint32_t AH0 = sb, AH1 = sb + GA_BYTES;
    const uint32_t BH  = sb + 2 * GA_BYTES, BL = BH + GA_BYTES;

    const int tid  = threadIdx.x;
    const int lane = tid & 31;
    const int wid  = tid >> 5;
    const int wm   = wid & 3;
    const int wn   = wid >> 2;
    const int bm   = blockIdx.y * 128;
    const int bn   = blockIdx.x * 128;

    float acc[2][8][4];
#pragma unroll
    for (int i = 0; i < 2; i++)
#pragma unroll
        for (int j = 0; j < 8; j++)
#pragma unroll
            for (int k = 0; k < 4; k++) acc[i][j][k] = 0.f;

    const uint32_t a_row = lane & 15;
    const uint32_t a_col = (lane >> 4) << 3;
    const uint32_t b_n   = (lane & 7) + ((lane >> 4) << 3);
    const uint32_t b_k   = ((lane >> 3) & 1) << 3;

    const int s_row = tid >> 2, s_c8 = tid & 3;
    const int w_row = tid >> 3, w_c4 = tid & 7;

    float4 vw[4];
#pragma unroll
    for (int i = 0; i < 2; i++) {
        int row = s_row + i * 64;
        CP_ASYNC16(AH0 + (row * LDH + s_c8 * 8) * 2,
                   A + (size_t)(bm + row) * K + s_c8 * 8);
    }
    CP_COMMIT;
#pragma unroll
    for (int i = 0; i < 4; i++) {
        int row = w_row + i * 32;
        vw[i] = *(const float4*)(W + (size_t)(bn + row) * K + w_c4 * 4);
    }

    const int nch = K / KC;
    for (int ch = 0; ch < nch; ch++) {
        const int kb = ch * KC;
        if (ch + 1 < nch) {
            uint32_t dst = ((ch + 1) & 1) ? AH1 : AH0;
#pragma unroll
            for (int i = 0; i < 2; i++) {
                int row = s_row + i * 64;
                CP_ASYNC16(dst + (row * LDH + s_c8 * 8) * 2,
                           A + (size_t)(bm + row) * K + kb + KC + s_c8 * 8);
            }
            CP_COMMIT;
        }
#pragma unroll
        for (int i = 0; i < 4; i++) {
            int row = w_row + i * 32;
            uint32_t off = (row * LDH + w_c4 * 4) * 2;
            splitw_store(BH + off, BL + off, vw[i]);
        }
        if (ch + 1 < nch) {
#pragma unroll
            for (int i = 0; i < 4; i++) {
                int row = w_row + i * 32;
                vw[i] = *(const float4*)(W + (size_t)(bn + row) * K + kb + KC + w_c4 * 4);
            }
        }
        if (ch + 1 < nch) { CP_WAIT_1; } else { CP_WAIT_0; }
        __syncthreads();

        const uint32_t AH = (ch & 1) ? AH1 : AH0;
#pragma unroll
        for (int ks = 0; ks < KC; ks += 16) {
            uint32_t ah[2][4];
#pragma unroll
            for (int ma = 0; ma < 2; ma++)
                ldsm4(ah[ma], AH + ((wm * 32 + ma * 16 + a_row) * LDH + ks + a_col) * 2);
#pragma unroll
            for (int bg = 0; bg < 4; bg++) {
                uint32_t boff = ((wn * 64 + bg * 16 + b_n) * LDH + ks + b_k) * 2;
                uint32_t bh[4], bl[4];
                ldsm4(bh, BH + boff);
                ldsm4(bl, BL + boff);
#pragma unroll
                for (int ma = 0; ma < 2; ma++) {
#pragma unroll
                    for (int na = 0; na < 2; na++) {
                        float* d = acc[ma][bg * 2 + na];
                        mma_f16(d, ah[ma], bh[na * 2], bh[na * 2 + 1]);
                        mma_f16(d, ah[ma], bl[na * 2], bl[na * 2 + 1]);
                    }
                }
            }
        }
        __syncthreads();
    }

#pragma unroll
    for (int ma = 0; ma < 2; ma++) {
        int row0 = bm + wm * 32 + ma * 16 + (lane >> 2);
#pragma unroll
        for (int na = 0; na < 8; na++) {
            int col = bn + wn * 64 + na * 8 + (lane & 3) * 2;
            float b0 = bias[col], b1 = bias[col + 1];
            *(uint32_t*)(C + (size_t)row0 * N + col) =
                pack_h2(acc[ma][na][0] + b0, acc[ma][na][1] + b1);
            *(uint32_t*)(C + (size_t)(row0 + 8) * N + col) =
                pack_h2(acc[ma][na][2] + b0, acc[ma][na][3] + b1);
        }
    }
}

__device__ __forceinline__ float sigmoidf_(float v) { return 1.f / (1.f + expf(-v)); }

// ========================= tensor-core LSTM scan (R9 machinery + fixes) ======
#define W_STR 520
#define A_STR 264
#define W_SPL_BYTES (32 * W_STR * 2)
#define SCAN_W_BYTES (2 * W_SPL_BYTES)                    // 66560
#define SCAN0_SMEM (SCAN_W_BYTES + 2 * 128 * A_STR * 2)   // 201728
#define SCAN1_SMEM (SCAN_W_BYTES + 2 * 64 * A_STR * 2)    // 134144

template<int MC>
__device__ __forceinline__ void stage_chunk(uint32_t dst, const __half* hs,
                                            int bbase, int kb, int tid) {
#pragma unroll
    for (int i = 0; i < MC / 8; i++) {
        int e = tid + i * 256;
        int row = e >> 5, seg = e & 31;
        const __half* src = hs + (size_t)(bbase + row) * HH + kb + seg * 8;
        CP_ASYNC16(dst + (row * A_STR + seg * 8) * 2, src);
    }
}

__device__ __forceinline__ void mma_chunk(uint32_t AB, uint32_t WHI, uint32_t WLO,
                                          int mrow, int kg0,
                                          uint32_t a_row, uint32_t a_col,
                                          uint32_t b_n, uint32_t b_k,
                                          float acc[4][4]) {
#pragma unroll
    for (int kk = 0; kk < 16; kk++) {
        uint32_t a[4];
        ldsm4(a, AB + ((mrow + a_row) * A_STR + kk * 16 + a_col) * 2);
        int kg = kg0 + kk * 16;
        uint32_t bh0[4], bh1[4], bl0[4], bl1[4];
        ldsm4(bh0, WHI + (b_n * W_STR + kg + b_k) * 2);
        ldsm4(bh1, WHI + ((16 + b_n) * W_STR + kg + b_k) * 2);
        ldsm4(bl0, WLO + (b_n * W_STR + kg + b_k) * 2);
        ldsm4(bl1, WLO + ((16 + b_n) * W_STR + kg + b_k) * 2);
        mma_f16(acc[0], a, bh0[0], bh0[1]);
        mma_f16(acc[0], a, bl0[0], bl0[1]);
        mma_f16(acc[1], a, bh0[2], bh0[3]);
        mma_f16(acc[1], a, bl0[2], bl0[3]);
        mma_f16(acc[2], a, bh1[0], bh1[1]);
        mma_f16(acc[2], a, bl1[0], bl1[1]);
        mma_f16(acc[3], a, bh1[2], bh1[3]);
        mma_f16(acc[3], a, bl1[2], bl1[3]);
    }
}

template<bool L0>
__global__ __launch_bounds__(256, 1) void scan_mma(
    const __half* __restrict__ xgf, const __half* __restrict__ xgr,
    const float* __restrict__ whhf, const float* __restrict__ whhr,
    const float* __restrict__ bhhf, const float* __restrict__ bhhr,
    __half* __restrict__ hrec, float* __restrict__ houtf,
    __half* __restrict__ houth, int* __restrict__ bar) {
    constexpr int MC = L0 ? 128 : 64;
    constexpr int ASZ = MC * A_STR * 2;
    extern __shared__ __align__(16) char smem[];
    const uint32_t sb  = smem_to_u32(smem);
    const uint32_t WHI = sb, WLO = sb + W_SPL_BYTES;
    const uint32_t AB0 = sb + SCAN_W_BYTES, AB1 = AB0 + ASZ;

    const int tid = threadIdx.x, lane = tid & 31, wid = tid >> 5;
    const int grp   = blockIdx.x >> 6;
    const int slice = blockIdx.x & 63;
    const int j0    = slice * 8;
    const int bbase = L0 ? 0 : grp * 64;
    const int bsub  = slice & 7;

    const float* whh = (L0 && grp) ? whhr : whhf;
    const float* bhh = (L0 && grp) ? bhhr : bhhf;
    const __half* xg = (L0 && grp) ? xgr  : xgf;
    int* barp = bar + grp * BAR_GRP;
    __half* hbuf = hrec + (L0 ? (size_t)grp * 2 * BB * HH : 0);

#pragma unroll
    for (int i = 0; i < 16; i++) {
        int idx = tid + i * 256;
        int n = idx >> 7, c4 = idx & 127;
        int grow = (n >> 3) * 512 + j0 + (n & 7);
        float4 v = *(const float4*)(whh + (size_t)grow * 512 + c4 * 4);
        uint32_t off = (n * W_STR + c4 * 4) * 2;
        splitw_store(WHI + off, WLO + off, v);
    }
    __syncthreads();

    const uint32_t a_row = lane & 15;
    const uint32_t a_col = (lane >> 4) << 3;
    const uint32_t b_n   = (lane & 7) + ((lane >> 4) << 3);
    const uint32_t b_k   = ((lane >> 3) & 1) << 3;
    const int r = lane >> 2;
    const int u = (lane & 3) * 2;
    const int wm = L0 ? wid : (wid & 3);
    const int mrow = wm * 16;
    const bool owner = L0 || (wid < 4);

    float bias[4][2];
#pragma unroll
    for (int g = 0; g < 4; g++) {
        bias[g][0] = bhh[g * 512 + j0 + u];
        bias[g][1] = bhh[g * 512 + j0 + u + 1];
    }
    float c[4] = {0.f, 0.f, 0.f, 0.f};

    // prologue xg prefetch (step 0)
    uint32_t xrn[4][2];
    if (owner) {
        const int t0 = (L0 && grp) ? (TT - 1) : 0;
        const __half* xp = xg + ((size_t)(t0 * BB + bbase + mrow + r)) * G4H + j0 + u;
#pragma unroll
        for (int g = 0; g < 4; g++)
#pragma unroll
            for (int rp = 0; rp < 2; rp++)
                xrn[g][rp] = *(const uint32_t*)(xp + (size_t)rp * 8 * G4H + g * 512);
    }

    for (int step = 0; step < TT; step++) {
        const int t = (L0 && grp) ? (TT - 1 - step) : step;

        uint32_t xr[4][2];
#pragma unroll
        for (int g = 0; g < 4; g++)
#pragma unroll
            for (int rp = 0; rp < 2; rp++) xr[g][rp] = xrn[g][rp];

        float acc[4][4];
#pragma unroll
        for (int g = 0; g < 4; g++)
#pragma unroll
            for (int k = 0; k < 4; k++) acc[g][k] = 0.f;

        if (step > 0) {
            const int rpar = (step - 1) & 1;
            const __half* hs = hbuf + (size_t)rpar * BB * HH;
            stage_chunk<MC>(AB0, hs, bbase, 0, tid);   CP_COMMIT;
            stage_chunk<MC>(AB1, hs, bbase, 256, tid); CP_COMMIT;
            if (L0) {
                CP_WAIT_1;
                __syncthreads();
                mma_chunk(AB0, WHI, WLO, mrow, 0, a_row, a_col, b_n, b_k, acc);
                CP_WAIT_0;
                __syncthreads();
                mma_chunk(AB1, WHI, WLO, mrow, 256, a_row, a_col, b_n, b_k, acc);
            } else {
                CP_WAIT_0;
                __syncthreads();
                const int ks = wid >> 2;
                mma_chunk(ks ? AB1 : AB0, WHI, WLO, mrow, ks * 256,
                          a_row, a_col, b_n, b_k, acc);
            }
        }

        if (!L0) {
            __syncthreads();
            if (wid >= 4) {
                uint32_t base = AB0 + ((wid - 4) * 32 + lane) * 4;
#pragma unroll
                for (int f = 0; f < 16; f++)
                    *(float*)(smem + (base - sb) + f * 512) = acc[f >> 2][f & 3];
            }
            __syncthreads();
            if (wid < 4) {
                uint32_t base = AB0 + (wid * 32 + lane) * 4;
#pragma unroll
                for (int f = 0; f < 16; f++)
                    acc[f >> 2][f & 3] += *(float*)(smem + (base - sb) + f * 512);
            }
        }

        if (owner) {
            const int wpar = step & 1;
            __half* dh = hbuf + (size_t)wpar * BB * HH;
#pragma unroll
            for (int rp = 0; rp < 2; rp++) {
                const int b = bbase + mrow + r + rp * 8;
                float hv2[2];
#pragma unroll
                for (int cc = 0; cc < 2; cc++) {
                    const int k = rp * 2 + cc;
                    float2 x0 = __half22float2(*(__half2*)&xr[0][rp]);
                    float2 x1 = __half22float2(*(__half2*)&xr[1][rp]);
                    float2 x2 = __half22float2(*(__half2*)&xr[2][rp]);
                    float2 x3 = __half22float2(*(__half2*)&xr[3][rp]);
                    float gi = acc[0][k] + (cc ? x0.y : x0.x) + bias[0][cc];
                    float gf = acc[1][k] + (cc ? x1.y : x1.x) + bias[1][cc];
                    float gg = acc[2][k] + (cc ? x2.y : x2.x) + bias[2][cc];
                    float go = acc[3][k] + (cc ? x3.y : x3.x) + bias[3][cc];
                    float cv = sigmoidf_(gf) * c[k] + sigmoidf_(gi) * tanhf(gg);
                    c[k] = cv;
                    hv2[cc] = sigmoidf_(go) * tanhf(cv);
                }
                if (L0) {
                    *(uint32_t*)(houth + ((size_t)(t * BB + b)) * 1024 + grp * 512 + j0 + u) =
                        pack_h2(hv2[0], hv2[1]);
                } else if (t == TT - 1) {
                    *(float2*)(houtf + (size_t)b * HH + j0 + u) =
                        make_float2(hv2[0], hv2[1]);
                }
                *(uint32_t*)(dh + (size_t)b * HH + j0 + u) = pack_h2(hv2[0], hv2[1]);
            }
        }

        if (step < TT - 1) {
            // prefetch next step's xg BEFORE the barrier (overlaps latency)
            if (owner) {
                const int tn = (L0 && grp) ? (TT - 2 - step) : (step + 1);
                const __half* xp = xg + ((size_t)(tn * BB + bbase + mrow + r)) * G4H + j0 + u;
#pragma unroll
                for (int g = 0; g < 4; g++)
#pragma unroll
                    for (int rp = 0; rp < 2; rp++)
                        xrn[g][rp] = *(const uint32_t*)(xp + (size_t)rp * 8 * G4H + g * 512);
            }
            __threadfence();
            __syncthreads();
            if (tid == 0)
                bar_arrive_wait(barp + step * BAR_STEP, bsub, 64);
            __syncthreads();
        }
    }
}

// ========================= layer-1 reverse at t = T-1 ========================
__global__ void hr_last_kernel(const __half* __restrict__ xg,
                               const float* __restrict__ bhh,
                               float* __restrict__ hr) {
    int idx = blockIdx.x * blockDim.x + threadIdx.x;
    if (idx >= BB * HH) return;
    int b = idx >> 9, j = idx & 511;
    float gi = __half2float(xg[(size_t)b * G4H + j])        + bhh[j];
    float gg = __half2float(xg[(size_t)b * G4H + 1024 + j]) + bhh[1024 + j];
    float go = __half2float(xg[(size_t)b * G4H + 1536 + j]) + bhh[1536 + j];
    float cv = sigmoidf_(gi) * tanhf(gg);
    hr[idx] = sigmoidf_(go) * tanhf(cv);
}

// ========================= final projection ==================================
__global__ void out_kernel(const float* __restrict__ hf, const float* __restrict__ hr,
                           const float* __restrict__ wout, const float* __restrict__ bout,
                           float* __restrict__ out) {
    int b = blockIdx.x;
    int warp = threadIdx.x >> 5;
    int lane = threadIdx.x & 31;
    float s = 0.f;
    for (int k = lane; k < 512; k += 32) s += hf[(size_t)b * HH + k] * wout[warp * 1024 + k];
    for (int k = lane; k < 512; k += 32) s += hr[(size_t)b * HH + k] * wout[warp * 1024 + 512 + k];
#pragma unroll
    for (int off = 16; off; off >>= 1) s += __shfl_xor_sync(0xffffffffu, s, off);
    if (lane == 0) out[b * NCLS + warp] = s + bout[warp];
}

// ========================= host launch =======================================
extern "C" void kernel_launch(void* const* d_in, const int* in_sizes, int n_in,
                              void* d_out, int out_size) {
    const int*   x     = (const int*)  d_in[0];
    const float* emb   = (const float*)d_in[1];
    const float* wih0f = (const float*)d_in[2];
    const float* whh0f = (const float*)d_in[3];
    const float* bih0f = (const float*)d_in[4];
    const float* bhh0f = (const float*)d_in[5];
    const float* wih0r = (const float*)d_in[6];
    const float* whh0r = (const float*)d_in[7];
    const float* bih0r = (const float*)d_in[8];
    const float* bhh0r = (const float*)d_in[9];
    const float* wih1f = (const float*)d_in[10];
    const float* whh1f = (const float*)d_in[11];
    const float* bih1f = (const float*)d_in[12];
    const float* bhh1f = (const float*)d_in[13];
    const float* wih1r = (const float*)d_in[14];
    const float* whh1r = (const float*)d_in[15]; (void)whh1r;
    const float* bih1r = (const float*)d_in[16];
    const float* bhh1r = (const float*)d_in[17];
    const float* wout  = (const float*)d_in[18];
    const float* bout  = (const float*)d_in[19];
    float* out = (float*)d_out;

    __half *p_x0, *p_h0, *p_hf0, *p_hf1, *p_xg0f, *p_xg0r, *p_xg1f, *p_xg1r;
    float *p_h1f, *p_hr1;
    int *p_bar0, *p_bar1;
    cudaGetSymbolAddress((void**)&p_x0,   g_x0);
    cudaGetSymbolAddress((void**)&p_xg0f, g_xg0f);
    cudaGetSymbolAddress((void**)&p_xg0r, g_xg0r);
    cudaGetSymbolAddress((void**)&p_h0,   g_h0);
    cudaGetSymbolAddress((void**)&p_xg1f, g_xg1f);
    cudaGetSymbolAddress((void**)&p_xg1r, g_xg1r);
    cudaGetSymbolAddress((void**)&p_hf0,  g_hf0);
    cudaGetSymbolAddress((void**)&p_hf1,  g_hf1);
    cudaGetSymbolAddress((void**)&p_h1f,  g_h1f);
    cudaGetSymbolAddress((void**)&p_hr1,  g_hr1);
    cudaGetSymbolAddress((void**)&p_bar0, g_bar0);
    cudaGetSymbolAddress((void**)&p_bar1, g_bar1);

    cudaFuncSetAttribute(scan_mma<true>,  cudaFuncAttributeMaxDynamicSharedMemorySize, SCAN0_SMEM);
    cudaFuncSetAttribute(scan_mma<false>, cudaFuncAttributeMaxDynamicSharedMemorySize, SCAN1_SMEM);

    reset_kernel<<<128, 256>>>();
    embed_kernel<<<(TT * BB * (DEMB / 4) + 255) / 256, 256>>>(x, emb, p_x0);

    dim3 gBig(G4H / 128, (TT * BB) / 128);   // (16, 256)
    gemm_mma<<<gBig, 256>>>(p_x0, wih0f, bih0f, p_xg0f, TT * BB, G4H, DEMB);
    gemm_mma<<<gBig, 256>>>(p_x0, wih0r, bih0r, p_xg0r, TT * BB, G4H, DEMB);

    scan_mma<true><<<128, 256, SCAN0_SMEM>>>(p_xg0f, p_xg0r, whh0f, whh0r,
                                             bhh0f, bhh0r, p_hf0, nullptr,
                                             p_h0, p_bar0);

    gemm_mma<<<gBig, 256>>>(p_h0, wih1f, bih1f, p_xg1f, TT * BB, G4H, 2 * HH);
    gemm_mma<<<dim3(G4H / 128, 1), 256>>>(
        p_h0 + (size_t)(TT - 1) * BB * 1024, wih1r, bih1r, p_xg1r, BB, G4H, 2 * HH);

    scan_mma<false><<<128, 256, SCAN1_SMEM>>>(p_xg1f, p_xg1f, whh1f, whh1f,
                                              bhh1f, bhh1f, p_hf1, p_h1f,
                                              nullptr, p_bar1);

    hr_last_kernel<<<(BB * HH) / 256, 256>>>(p_xg1r, bhh1r, p_hr1);

    out_kernel<<<BB, 160>>>(p_h1f, p_hr1, wout, bout, out);
}